// round 2
// baseline (speedup 1.0000x reference)
#include <cuda_runtime.h>
#include <cstdint>

#define N0 900000
#define N1C 43008
#define N2C 2048
#define D 64
#define TWO_D 128
#define E0MAX (43008 * 20)
#define E1MAX (2048 * 20)

// ---------------- device-global scratch (no allocations allowed) ----------
__device__ float g_agg0[N1C * D];
__device__ float g_cnt0[N1C];
__device__ float g_h1[N1C * D];
__device__ float g_agg1[N2C * D];
__device__ float g_cnt1[N2C];

__device__ int g_cnti0[N1C];
__device__ int g_off0[N1C + 1];
__device__ int g_pos0[N1C];
__device__ int g_csrc0[E0MAX];

__device__ int g_cnti1[N2C];
__device__ int g_off1[N2C + 1];
__device__ int g_pos1[N2C];
__device__ int g_csrc1[E1MAX];

// ---------------- CSR build: histogram ------------------------------------
__global__ void hist_kernel(const int* __restrict__ edst,
                            int* __restrict__ cnti, int E) {
    int e = blockIdx.x * blockDim.x + threadIdx.x;
    if (e < E) atomicAdd(&cnti[edst[e]], 1);
}

// ---------------- CSR build: single-block scan -----------------------------
__global__ void scan_kernel(const int* __restrict__ cnt,
                            int* __restrict__ off,
                            int* __restrict__ pos, int n) {
    __shared__ int sums[1024];
    int tid = threadIdx.x;
    int chunk = (n + 1023) >> 10;
    int beg = min(tid * chunk, n);
    int end = min(beg + chunk, n);
    int s = 0;
    for (int i = beg; i < end; i++) s += cnt[i];
    sums[tid] = s;
    __syncthreads();
    for (int d = 1; d < 1024; d <<= 1) {
        int v = 0;
        if (tid >= d) v = sums[tid - d];
        __syncthreads();
        sums[tid] += v;
        __syncthreads();
    }
    int run = (tid == 0) ? 0 : sums[tid - 1];
    for (int i = beg; i < end; i++) {
        off[i] = run;
        pos[i] = run;
        run += cnt[i];
    }
    if (tid == 1023) off[n] = sums[1023];
}

// ---------------- CSR build: fill src lists --------------------------------
__global__ void fill_kernel(const int* __restrict__ esrc,
                            const int* __restrict__ edst,
                            int* __restrict__ pos,
                            int* __restrict__ csrc, int E) {
    int e = blockIdx.x * blockDim.x + threadIdx.x;
    if (e < E) {
        int p = atomicAdd(&pos[edst[e]], 1);
        csrc[p] = esrc[e];
    }
}

// ---------------- gather + sum (per-target, register accumulation) ---------
// 16 lanes per target, lane owns one float4 of the 64-float row.
__global__ void gather_sum_kernel(const float* __restrict__ src_feat,
                                  const int* __restrict__ csrc,
                                  const int* __restrict__ off,
                                  float* __restrict__ agg,
                                  float* __restrict__ cnt, int n) {
    int t = blockIdx.x * blockDim.x + threadIdx.x;
    int g = t >> 4;
    if (g >= n) return;
    int l = t & 15;
    int beg = off[g];
    int end = off[g + 1];
    const float4* base = reinterpret_cast<const float4*>(src_feat);
    float4 acc = make_float4(0.f, 0.f, 0.f, 0.f);
    int e = beg;
    for (; e + 4 <= end; e += 4) {
        int s0 = csrc[e], s1 = csrc[e + 1], s2 = csrc[e + 2], s3 = csrc[e + 3];
        float4 v0 = base[(size_t)s0 * 16 + l];
        float4 v1 = base[(size_t)s1 * 16 + l];
        float4 v2 = base[(size_t)s2 * 16 + l];
        float4 v3 = base[(size_t)s3 * 16 + l];
        acc.x += (v0.x + v1.x) + (v2.x + v3.x);
        acc.y += (v0.y + v1.y) + (v2.y + v3.y);
        acc.z += (v0.z + v1.z) + (v2.z + v3.z);
        acc.w += (v0.w + v1.w) + (v2.w + v3.w);
    }
    for (; e < end; e++) {
        int s = csrc[e];
        float4 v = base[(size_t)s * 16 + l];
        acc.x += v.x; acc.y += v.y; acc.z += v.z; acc.w += v.w;
    }
    reinterpret_cast<float4*>(agg)[(size_t)g * 16 + l] = acc;
    if (l == 0) cnt[g] = (float)(end - beg);
}

// ---------------- fused concat + mean + GEMM (+bias, optional relu) -------
// 64 rows/block, 256 threads, each thread: 4 rows x 4 cols.
template <bool RELU>
__global__ void sage_gemm_kernel(const float* __restrict__ self_feat,
                                 const float* __restrict__ agg,
                                 const float* __restrict__ cnt,
                                 const float* __restrict__ w,   // [2D][D]
                                 const float* __restrict__ b,   // [D]
                                 float* __restrict__ out, int n) {
    extern __shared__ float sm[];
    float* wsh  = sm;                       // 128*64
    float* insh = sm + TWO_D * D;           // 64*129
    float* scl  = insh + 64 * 129;          // 64

    const int tid = threadIdx.x;
    const int tx = tid & 15;
    const int ty = tid >> 4;
    const int row0 = blockIdx.x * 64;

    if (tid < 64) {
        int r = row0 + tid;
        float c = (r < n) ? cnt[r] : 1.0f;
        scl[tid] = 1.0f / fmaxf(c, 1.0f);
    }
    #pragma unroll 4
    for (int i = tid; i < TWO_D * D; i += 256) wsh[i] = w[i];
    __syncthreads();

    for (int i = tid; i < 64 * TWO_D; i += 256) {
        int r = i >> 7;
        int k = i & 127;
        int row = row0 + r;
        float v = 0.0f;
        if (row < n) {
            v = (k < D) ? self_feat[(size_t)row * D + k]
                        : agg[(size_t)row * D + (k - D)] * scl[r];
        }
        insh[r * 129 + k] = v;
    }
    __syncthreads();

    float4 bias = *reinterpret_cast<const float4*>(b + tx * 4);
    float4 acc0 = bias, acc1 = bias, acc2 = bias, acc3 = bias;
    const float* in0 = insh + (ty * 4 + 0) * 129;
    const float* in1 = insh + (ty * 4 + 1) * 129;
    const float* in2 = insh + (ty * 4 + 2) * 129;
    const float* in3 = insh + (ty * 4 + 3) * 129;

    #pragma unroll 8
    for (int k = 0; k < TWO_D; k++) {
        float4 wv = *reinterpret_cast<const float4*>(wsh + k * D + tx * 4);
        float a0 = in0[k], a1 = in1[k], a2 = in2[k], a3 = in3[k];
        acc0.x = fmaf(a0, wv.x, acc0.x); acc0.y = fmaf(a0, wv.y, acc0.y);
        acc0.z = fmaf(a0, wv.z, acc0.z); acc0.w = fmaf(a0, wv.w, acc0.w);
        acc1.x = fmaf(a1, wv.x, acc1.x); acc1.y = fmaf(a1, wv.y, acc1.y);
        acc1.z = fmaf(a1, wv.z, acc1.z); acc1.w = fmaf(a1, wv.w, acc1.w);
        acc2.x = fmaf(a2, wv.x, acc2.x); acc2.y = fmaf(a2, wv.y, acc2.y);
        acc2.z = fmaf(a2, wv.z, acc2.z); acc2.w = fmaf(a2, wv.w, acc2.w);
        acc3.x = fmaf(a3, wv.x, acc3.x); acc3.y = fmaf(a3, wv.y, acc3.y);
        acc3.z = fmaf(a3, wv.z, acc3.z); acc3.w = fmaf(a3, wv.w, acc3.w);
    }

    if (RELU) {
        acc0.x = fmaxf(acc0.x, 0.f); acc0.y = fmaxf(acc0.y, 0.f);
        acc0.z = fmaxf(acc0.z, 0.f); acc0.w = fmaxf(acc0.w, 0.f);
        acc1.x = fmaxf(acc1.x, 0.f); acc1.y = fmaxf(acc1.y, 0.f);
        acc1.z = fmaxf(acc1.z, 0.f); acc1.w = fmaxf(acc1.w, 0.f);
        acc2.x = fmaxf(acc2.x, 0.f); acc2.y = fmaxf(acc2.y, 0.f);
        acc2.z = fmaxf(acc2.z, 0.f); acc2.w = fmaxf(acc2.w, 0.f);
        acc3.x = fmaxf(acc3.x, 0.f); acc3.y = fmaxf(acc3.y, 0.f);
        acc3.z = fmaxf(acc3.z, 0.f); acc3.w = fmaxf(acc3.w, 0.f);
    }

    int r0 = row0 + ty * 4;
    if (r0 + 0 < n) *reinterpret_cast<float4*>(out + (size_t)(r0 + 0) * D + tx * 4) = acc0;
    if (r0 + 1 < n) *reinterpret_cast<float4*>(out + (size_t)(r0 + 1) * D + tx * 4) = acc1;
    if (r0 + 2 < n) *reinterpret_cast<float4*>(out + (size_t)(r0 + 2) * D + tx * 4) = acc2;
    if (r0 + 3 < n) *reinterpret_cast<float4*>(out + (size_t)(r0 + 3) * D + tx * 4) = acc3;
}

static const int SMEM_GEMM = (TWO_D * D + 64 * 129 + 64) * (int)sizeof(float);

// ---------------- launch ---------------------------------------------------
extern "C" void kernel_launch(void* const* d_in, const int* in_sizes, int n_in,
                              void* d_out, int out_size) {
    const float* x         = (const float*)d_in[0];
    const float* w0        = (const float*)d_in[1];
    const float* b0        = (const float*)d_in[2];
    const float* w1        = (const float*)d_in[3];
    const float* b1        = (const float*)d_in[4];
    const int*   edge_src0 = (const int*)d_in[5];
    const int*   edge_dst0 = (const int*)d_in[6];
    const int*   edge_src1 = (const int*)d_in[7];
    const int*   edge_dst1 = (const int*)d_in[8];
    const int E0 = in_sizes[5];
    const int E1 = in_sizes[7];

    float *agg0, *cnt0, *h1, *agg1, *cnt1;
    int *cnti0, *off0, *pos0, *csrc0, *cnti1, *off1, *pos1, *csrc1;
    cudaGetSymbolAddress((void**)&agg0, g_agg0);
    cudaGetSymbolAddress((void**)&cnt0, g_cnt0);
    cudaGetSymbolAddress((void**)&h1,   g_h1);
    cudaGetSymbolAddress((void**)&agg1, g_agg1);
    cudaGetSymbolAddress((void**)&cnt1, g_cnt1);
    cudaGetSymbolAddress((void**)&cnti0, g_cnti0);
    cudaGetSymbolAddress((void**)&off0,  g_off0);
    cudaGetSymbolAddress((void**)&pos0,  g_pos0);
    cudaGetSymbolAddress((void**)&csrc0, g_csrc0);
    cudaGetSymbolAddress((void**)&cnti1, g_cnti1);
    cudaGetSymbolAddress((void**)&off1,  g_off1);
    cudaGetSymbolAddress((void**)&pos1,  g_pos1);
    cudaGetSymbolAddress((void**)&csrc1, g_csrc1);

    cudaFuncSetAttribute(sage_gemm_kernel<true>,
                         cudaFuncAttributeMaxDynamicSharedMemorySize, SMEM_GEMM);
    cudaFuncSetAttribute(sage_gemm_kernel<false>,
                         cudaFuncAttributeMaxDynamicSharedMemorySize, SMEM_GEMM);

    // zero histogram counters only (agg/cnt written unconditionally by gather)
    cudaMemsetAsync(cnti0, 0, N1C * sizeof(int), 0);
    cudaMemsetAsync(cnti1, 0, N2C * sizeof(int), 0);

    // ---- layer 0 ----
    hist_kernel<<<(E0 + 255) / 256, 256>>>(edge_dst0, cnti0, E0);
    scan_kernel<<<1, 1024>>>(cnti0, off0, pos0, N1C);
    fill_kernel<<<(E0 + 255) / 256, 256>>>(edge_src0, edge_dst0, pos0, csrc0, E0);
    {
        int threads = N1C * 16;
        gather_sum_kernel<<<(threads + 255) / 256, 256>>>(x, csrc0, off0,
                                                          agg0, cnt0, N1C);
    }
    sage_gemm_kernel<true><<<N1C / 64, 256, SMEM_GEMM>>>(x, agg0, cnt0,
                                                         w0, b0, h1, N1C);

    // ---- layer 1 ----
    hist_kernel<<<(E1 + 255) / 256, 256>>>(edge_dst1, cnti1, E1);
    scan_kernel<<<1, 1024>>>(cnti1, off1, pos1, N2C);
    fill_kernel<<<(E1 + 255) / 256, 256>>>(edge_src1, edge_dst1, pos1, csrc1, E1);
    {
        int threads = N2C * 16;
        gather_sum_kernel<<<(threads + 255) / 256, 256>>>(h1, csrc1, off1,
                                                          agg1, cnt1, N2C);
    }
    sage_gemm_kernel<false><<<N2C / 64, 256, SMEM_GEMM>>>(h1, agg1, cnt1,
                                                          w1, b1,
                                                          (float*)d_out, N2C);
}

// round 3
// speedup vs baseline: 1.1304x; 1.1304x over previous
#include <cuda_runtime.h>
#include <cstdint>

#define N0 900000
#define N1C 43008
#define N2C 2048
#define D 64
#define TWO_D 128
#define E0C (N1C * 20)
#define E1C (N2C * 20)
#define INSTRIDE 132   // 128 + 4 pad (keeps float4 alignment, skews banks)

// ---------------- device-global scratch ------------------------------------
__device__ float g_h1[N1C * D];
__device__ int g_cnti[N1C + N2C];     // single memset target
__device__ int g_off0[N1C + 1];
__device__ int g_off1[N2C + 1];
__device__ int g_pos0[N1C];
__device__ int g_pos1[N2C];
__device__ int g_csrc0[E0C];
__device__ int g_csrc1[E1C];

// ---------------- fused histogram (both layers) ----------------------------
__global__ void hist2_kernel(const int* __restrict__ ed0,
                             const int* __restrict__ ed1,
                             int* __restrict__ c0, int* __restrict__ c1,
                             int E0, int E1) {
    int e = blockIdx.x * blockDim.x + threadIdx.x;
    if (e < E0) atomicAdd(&c0[ed0[e]], 1);
    else if (e < E0 + E1) atomicAdd(&c1[ed1[e - E0]], 1);
}

// ---------------- fused scan (block 0: layer0, block 1: layer1) ------------
__global__ void scan2_kernel(const int* __restrict__ c0, int* __restrict__ o0,
                             int* __restrict__ p0, int n0,
                             const int* __restrict__ c1, int* __restrict__ o1,
                             int* __restrict__ p1, int n1) {
    __shared__ int sums[1024];
    const int* c; int* o; int* p; int n;
    if (blockIdx.x == 0) { c = c0; o = o0; p = p0; n = n0; }
    else                 { c = c1; o = o1; p = p1; n = n1; }
    int tid = threadIdx.x;
    int chunk = (n + 1023) >> 10;
    int beg = min(tid * chunk, n);
    int end = min(beg + chunk, n);
    int s = 0;
    for (int i = beg; i < end; i++) s += c[i];
    sums[tid] = s;
    __syncthreads();
    for (int d = 1; d < 1024; d <<= 1) {
        int v = 0;
        if (tid >= d) v = sums[tid - d];
        __syncthreads();
        sums[tid] += v;
        __syncthreads();
    }
    int run = (tid == 0) ? 0 : sums[tid - 1];
    for (int i = beg; i < end; i++) {
        o[i] = run;
        p[i] = run;
        run += c[i];
    }
    if (tid == 1023) o[n] = sums[1023];
}

// ---------------- fused fill (both layers) ---------------------------------
__global__ void fill2_kernel(const int* __restrict__ es0, const int* __restrict__ ed0,
                             int* __restrict__ p0, int* __restrict__ cs0,
                             const int* __restrict__ es1, const int* __restrict__ ed1,
                             int* __restrict__ p1, int* __restrict__ cs1,
                             int E0, int E1) {
    int e = blockIdx.x * blockDim.x + threadIdx.x;
    if (e < E0) {
        int q = atomicAdd(&p0[ed0[e]], 1);
        cs0[q] = es0[e];
    } else if (e < E0 + E1) {
        int e1 = e - E0;
        int q = atomicAdd(&p1[ed1[e1]], 1);
        cs1[q] = es1[e1];
    }
}

// ---------------- fused gather + mean + concat-GEMM ------------------------
// Persistent blocks. 256 threads / 64-row tile.
// Phase A: stage self rows + gathered-mean rows into concat smem tile.
// Phase B: [64x128] @ [128x64] GEMM, thread = 4 rows x 4 cols.
template <bool RELU>
__global__ void fused_sage_kernel(const float* __restrict__ gather_feat,
                                  const float* __restrict__ self_feat,
                                  const int* __restrict__ csrc,
                                  const int* __restrict__ off,
                                  const float* __restrict__ w,   // [2D][D]
                                  const float* __restrict__ b,   // [D]
                                  float* __restrict__ out,
                                  int ntiles) {
    extern __shared__ float sm[];
    float* wsh  = sm;                 // 128*64 = 8192 floats
    float* insh = sm + TWO_D * D;     // 64*132 = 8448 floats

    const int tid = threadIdx.x;
    const int tx = tid & 15;          // col group (4 cols)
    const int ty = tid >> 4;          // row group (4 rows)

    // weights once per block
    for (int i = tid; i < TWO_D * D / 4; i += 256)
        reinterpret_cast<float4*>(wsh)[i] = reinterpret_cast<const float4*>(w)[i];
    const float4 bias = reinterpret_cast<const float4*>(b)[tx];
    __syncthreads();

    const float4* gbase = reinterpret_cast<const float4*>(gather_feat);
    const float4* sbase = reinterpret_cast<const float4*>(self_feat);

    for (int tile = blockIdx.x; tile < ntiles; tile += gridDim.x) {
        const int row0 = tile * 64;

        // self rows -> insh[r][0:64]
        for (int i = tid; i < 64 * 16; i += 256) {
            int r = i >> 4, l = i & 15;
            reinterpret_cast<float4*>(insh + r * INSTRIDE)[l] =
                sbase[(size_t)(row0 + r) * 16 + l];
        }

        // gather-mean -> insh[r][64:128]; group ty handles rows ty*4..+3
        #pragma unroll
        for (int j = 0; j < 4; j++) {
            int r = ty * 4 + j;
            int row = row0 + r;
            int beg = off[row];
            int end = off[row + 1];
            float4 acc = make_float4(0.f, 0.f, 0.f, 0.f);
            int e = beg;
            for (; e + 4 <= end; e += 4) {
                int s0 = csrc[e], s1 = csrc[e + 1];
                int s2 = csrc[e + 2], s3 = csrc[e + 3];
                float4 v0 = gbase[(size_t)s0 * 16 + tx];
                float4 v1 = gbase[(size_t)s1 * 16 + tx];
                float4 v2 = gbase[(size_t)s2 * 16 + tx];
                float4 v3 = gbase[(size_t)s3 * 16 + tx];
                acc.x += (v0.x + v1.x) + (v2.x + v3.x);
                acc.y += (v0.y + v1.y) + (v2.y + v3.y);
                acc.z += (v0.z + v1.z) + (v2.z + v3.z);
                acc.w += (v0.w + v1.w) + (v2.w + v3.w);
            }
            for (; e < end; e++) {
                int s = csrc[e];
                float4 v = gbase[(size_t)s * 16 + tx];
                acc.x += v.x; acc.y += v.y; acc.z += v.z; acc.w += v.w;
            }
            float scl = 1.0f / fmaxf((float)(end - beg), 1.0f);
            acc.x *= scl; acc.y *= scl; acc.z *= scl; acc.w *= scl;
            reinterpret_cast<float4*>(insh + r * INSTRIDE + D)[tx] = acc;
        }
        __syncthreads();

        // GEMM: 4 rows x 4 cols per thread
        float4 a0 = bias, a1 = bias, a2 = bias, a3 = bias;
        const float* i0 = insh + (ty * 4 + 0) * INSTRIDE;
        const float* i1 = insh + (ty * 4 + 1) * INSTRIDE;
        const float* i2 = insh + (ty * 4 + 2) * INSTRIDE;
        const float* i3 = insh + (ty * 4 + 3) * INSTRIDE;

        #pragma unroll 8
        for (int k = 0; k < TWO_D; k++) {
            float4 wv = *reinterpret_cast<const float4*>(wsh + k * D + tx * 4);
            float v0 = i0[k], v1 = i1[k], v2 = i2[k], v3 = i3[k];
            a0.x = fmaf(v0, wv.x, a0.x); a0.y = fmaf(v0, wv.y, a0.y);
            a0.z = fmaf(v0, wv.z, a0.z); a0.w = fmaf(v0, wv.w, a0.w);
            a1.x = fmaf(v1, wv.x, a1.x); a1.y = fmaf(v1, wv.y, a1.y);
            a1.z = fmaf(v1, wv.z, a1.z); a1.w = fmaf(v1, wv.w, a1.w);
            a2.x = fmaf(v2, wv.x, a2.x); a2.y = fmaf(v2, wv.y, a2.y);
            a2.z = fmaf(v2, wv.z, a2.z); a2.w = fmaf(v2, wv.w, a2.w);
            a3.x = fmaf(v3, wv.x, a3.x); a3.y = fmaf(v3, wv.y, a3.y);
            a3.z = fmaf(v3, wv.z, a3.z); a3.w = fmaf(v3, wv.w, a3.w);
        }

        if (RELU) {
            a0.x = fmaxf(a0.x, 0.f); a0.y = fmaxf(a0.y, 0.f);
            a0.z = fmaxf(a0.z, 0.f); a0.w = fmaxf(a0.w, 0.f);
            a1.x = fmaxf(a1.x, 0.f); a1.y = fmaxf(a1.y, 0.f);
            a1.z = fmaxf(a1.z, 0.f); a1.w = fmaxf(a1.w, 0.f);
            a2.x = fmaxf(a2.x, 0.f); a2.y = fmaxf(a2.y, 0.f);
            a2.z = fmaxf(a2.z, 0.f); a2.w = fmaxf(a2.w, 0.f);
            a3.x = fmaxf(a3.x, 0.f); a3.y = fmaxf(a3.y, 0.f);
            a3.z = fmaxf(a3.z, 0.f); a3.w = fmaxf(a3.w, 0.f);
        }

        int r0 = row0 + ty * 4;
        reinterpret_cast<float4*>(out + (size_t)(r0 + 0) * D)[tx] = a0;
        reinterpret_cast<float4*>(out + (size_t)(r0 + 1) * D)[tx] = a1;
        reinterpret_cast<float4*>(out + (size_t)(r0 + 2) * D)[tx] = a2;
        reinterpret_cast<float4*>(out + (size_t)(r0 + 3) * D)[tx] = a3;
        __syncthreads();   // before next tile overwrites insh
    }
}

static const int SMEM_FUSED = (TWO_D * D + 64 * INSTRIDE) * (int)sizeof(float);

// ---------------- launch ---------------------------------------------------
extern "C" void kernel_launch(void* const* d_in, const int* in_sizes, int n_in,
                              void* d_out, int out_size) {
    const float* x         = (const float*)d_in[0];
    const float* w0        = (const float*)d_in[1];
    const float* b0        = (const float*)d_in[2];
    const float* w1        = (const float*)d_in[3];
    const float* b1        = (const float*)d_in[4];
    const int*   edge_src0 = (const int*)d_in[5];
    const int*   edge_dst0 = (const int*)d_in[6];
    const int*   edge_src1 = (const int*)d_in[7];
    const int*   edge_dst1 = (const int*)d_in[8];
    const int E0 = in_sizes[5];
    const int E1 = in_sizes[7];

    float* h1;
    int *cnti, *off0, *off1, *pos0, *pos1, *csrc0, *csrc1;
    cudaGetSymbolAddress((void**)&h1,    g_h1);
    cudaGetSymbolAddress((void**)&cnti,  g_cnti);
    cudaGetSymbolAddress((void**)&off0,  g_off0);
    cudaGetSymbolAddress((void**)&off1,  g_off1);
    cudaGetSymbolAddress((void**)&pos0,  g_pos0);
    cudaGetSymbolAddress((void**)&pos1,  g_pos1);
    cudaGetSymbolAddress((void**)&csrc0, g_csrc0);
    cudaGetSymbolAddress((void**)&csrc1, g_csrc1);
    int* cnti0 = cnti;
    int* cnti1 = cnti + N1C;

    cudaFuncSetAttribute(fused_sage_kernel<true>,
                         cudaFuncAttributeMaxDynamicSharedMemorySize, SMEM_FUSED);
    cudaFuncSetAttribute(fused_sage_kernel<false>,
                         cudaFuncAttributeMaxDynamicSharedMemorySize, SMEM_FUSED);

    // 1 memset + 5 kernels total
    cudaMemsetAsync(cnti, 0, (N1C + N2C) * sizeof(int), 0);

    int EB = E0 + E1;
    hist2_kernel<<<(EB + 255) / 256, 256>>>(edge_dst0, edge_dst1,
                                            cnti0, cnti1, E0, E1);
    scan2_kernel<<<2, 1024>>>(cnti0, off0, pos0, N1C,
                              cnti1, off1, pos1, N2C);
    fill2_kernel<<<(EB + 255) / 256, 256>>>(edge_src0, edge_dst0, pos0, csrc0,
                                            edge_src1, edge_dst1, pos1, csrc1,
                                            E0, E1);

    fused_sage_kernel<true><<<444, 256, SMEM_FUSED>>>(x, x, csrc0, off0,
                                                      w0, b0, h1, N1C / 64);
    fused_sage_kernel<false><<<32, 256, SMEM_FUSED>>>(h1, h1, csrc1, off1,
                                                      w1, b1, (float*)d_out,
                                                      N2C / 64);
}

// round 4
// speedup vs baseline: 2.0888x; 1.8479x over previous
#include <cuda_runtime.h>
#include <cstdint>

#define N0 900000
#define N1C 43008
#define N2C 2048
#define D 64
#define TWO_D 128
#define CAP 96
#define INSTRIDE 132

// ---------------- device-global scratch ------------------------------------
__device__ float g_agg0[N1C * D];         // mean-aggregated neighbor feats L0
__device__ float g_h1[N1C * D];           // layer-0 output
__device__ float g_agg1[N2C * D];
__device__ int   g_cnti[N1C + N2C];       // degree counters (single memset)
__device__ int   g_slots0[N1C * CAP];     // capacity-slotted adjacency L0
__device__ int   g_slots1[N2C * CAP];

// ---------------- build: one atomic pass, no scan ---------------------------
__global__ void fill_kernel(const int* __restrict__ esrc,
                            const int* __restrict__ edst,
                            int* __restrict__ cnti,
                            int* __restrict__ slots, int E) {
    int e = blockIdx.x * blockDim.x + threadIdx.x;
    if (e >= E) return;
    int d = edst[e];
    int p = atomicAdd(&cnti[d], 1);
    if (p < CAP) slots[d * CAP + p] = esrc[e];
}

// ---------------- gather + mean (register accumulation) ---------------------
// 16 lanes per target; lane owns one float4 of the 64-float row. 8-wide unroll.
__global__ void gather_mean_kernel(const float* __restrict__ src_feat,
                                   const int* __restrict__ slots,
                                   const int* __restrict__ cnti,
                                   float* __restrict__ agg, int n) {
    int t = blockIdx.x * blockDim.x + threadIdx.x;
    int g = t >> 4;
    if (g >= n) return;
    int l = t & 15;
    int deg = cnti[g];
    int m = min(deg, CAP);
    const int* sl = slots + (size_t)g * CAP;
    const float4* base = reinterpret_cast<const float4*>(src_feat);
    float4 acc = make_float4(0.f, 0.f, 0.f, 0.f);
    int e = 0;
    for (; e + 8 <= m; e += 8) {
        int4 ia = *reinterpret_cast<const int4*>(sl + e);
        int4 ib = *reinterpret_cast<const int4*>(sl + e + 4);
        float4 v0 = base[(size_t)ia.x * 16 + l];
        float4 v1 = base[(size_t)ia.y * 16 + l];
        float4 v2 = base[(size_t)ia.z * 16 + l];
        float4 v3 = base[(size_t)ia.w * 16 + l];
        float4 v4 = base[(size_t)ib.x * 16 + l];
        float4 v5 = base[(size_t)ib.y * 16 + l];
        float4 v6 = base[(size_t)ib.z * 16 + l];
        float4 v7 = base[(size_t)ib.w * 16 + l];
        acc.x += ((v0.x + v1.x) + (v2.x + v3.x)) + ((v4.x + v5.x) + (v6.x + v7.x));
        acc.y += ((v0.y + v1.y) + (v2.y + v3.y)) + ((v4.y + v5.y) + (v6.y + v7.y));
        acc.z += ((v0.z + v1.z) + (v2.z + v3.z)) + ((v4.z + v5.z) + (v6.z + v7.z));
        acc.w += ((v0.w + v1.w) + (v2.w + v3.w)) + ((v4.w + v5.w) + (v6.w + v7.w));
    }
    for (; e < m; e++) {
        float4 v = base[(size_t)sl[e] * 16 + l];
        acc.x += v.x; acc.y += v.y; acc.z += v.z; acc.w += v.w;
    }
    float scl = 1.0f / fmaxf((float)deg, 1.0f);
    acc.x *= scl; acc.y *= scl; acc.z *= scl; acc.w *= scl;
    reinterpret_cast<float4*>(agg)[(size_t)g * 16 + l] = acc;
}

// ---------------- concat GEMM: 64 rows/block, thread = 4 rows x 4 cols ------
template <bool RELU>
__global__ void sage_gemm_kernel(const float* __restrict__ self_feat,
                                 const float* __restrict__ agg,   // already mean
                                 const float* __restrict__ w,     // [2D][D]
                                 const float* __restrict__ b,     // [D]
                                 float* __restrict__ out, int n) {
    extern __shared__ float sm[];
    float* wsh  = sm;                   // 8192 floats
    float* insh = sm + TWO_D * D;       // 64*132 floats

    const int tid = threadIdx.x;
    const int tx = tid & 15;
    const int ty = tid >> 4;
    const int row0 = blockIdx.x * 64;

    for (int i = tid; i < TWO_D * D / 4; i += 256)
        reinterpret_cast<float4*>(wsh)[i] = reinterpret_cast<const float4*>(w)[i];
    const float4 bias = reinterpret_cast<const float4*>(b)[tx];

    // stage: self -> [0:64), agg -> [64:128)
    const float4* sbase = reinterpret_cast<const float4*>(self_feat);
    const float4* abase = reinterpret_cast<const float4*>(agg);
    for (int i = tid; i < 64 * 16; i += 256) {
        int r = i >> 4, l = i & 15;
        size_t gi = (size_t)(row0 + r) * 16 + l;
        reinterpret_cast<float4*>(insh + r * INSTRIDE)[l] = sbase[gi];
        reinterpret_cast<float4*>(insh + r * INSTRIDE + D)[l] = abase[gi];
    }
    __syncthreads();

    float4 a0 = bias, a1 = bias, a2 = bias, a3 = bias;
    const float* i0 = insh + (ty * 4 + 0) * INSTRIDE;
    const float* i1 = insh + (ty * 4 + 1) * INSTRIDE;
    const float* i2 = insh + (ty * 4 + 2) * INSTRIDE;
    const float* i3 = insh + (ty * 4 + 3) * INSTRIDE;

    #pragma unroll 8
    for (int k = 0; k < TWO_D; k++) {
        float4 wv = *reinterpret_cast<const float4*>(wsh + k * D + tx * 4);
        float v0 = i0[k], v1 = i1[k], v2 = i2[k], v3 = i3[k];
        a0.x = fmaf(v0, wv.x, a0.x); a0.y = fmaf(v0, wv.y, a0.y);
        a0.z = fmaf(v0, wv.z, a0.z); a0.w = fmaf(v0, wv.w, a0.w);
        a1.x = fmaf(v1, wv.x, a1.x); a1.y = fmaf(v1, wv.y, a1.y);
        a1.z = fmaf(v1, wv.z, a1.z); a1.w = fmaf(v1, wv.w, a1.w);
        a2.x = fmaf(v2, wv.x, a2.x); a2.y = fmaf(v2, wv.y, a2.y);
        a2.z = fmaf(v2, wv.z, a2.z); a2.w = fmaf(v2, wv.w, a2.w);
        a3.x = fmaf(v3, wv.x, a3.x); a3.y = fmaf(v3, wv.y, a3.y);
        a3.z = fmaf(v3, wv.z, a3.z); a3.w = fmaf(v3, wv.w, a3.w);
    }

    if (RELU) {
        a0.x = fmaxf(a0.x, 0.f); a0.y = fmaxf(a0.y, 0.f);
        a0.z = fmaxf(a0.z, 0.f); a0.w = fmaxf(a0.w, 0.f);
        a1.x = fmaxf(a1.x, 0.f); a1.y = fmaxf(a1.y, 0.f);
        a1.z = fmaxf(a1.z, 0.f); a1.w = fmaxf(a1.w, 0.f);
        a2.x = fmaxf(a2.x, 0.f); a2.y = fmaxf(a2.y, 0.f);
        a2.z = fmaxf(a2.z, 0.f); a2.w = fmaxf(a2.w, 0.f);
        a3.x = fmaxf(a3.x, 0.f); a3.y = fmaxf(a3.y, 0.f);
        a3.z = fmaxf(a3.z, 0.f); a3.w = fmaxf(a3.w, 0.f);
    }

    int r0 = row0 + ty * 4;
    reinterpret_cast<float4*>(out + (size_t)(r0 + 0) * D)[tx] = a0;
    reinterpret_cast<float4*>(out + (size_t)(r0 + 1) * D)[tx] = a1;
    reinterpret_cast<float4*>(out + (size_t)(r0 + 2) * D)[tx] = a2;
    reinterpret_cast<float4*>(out + (size_t)(r0 + 3) * D)[tx] = a3;
}

static const int SMEM_GEMM = (TWO_D * D + 64 * INSTRIDE) * (int)sizeof(float);

// ---------------- launch ---------------------------------------------------
extern "C" void kernel_launch(void* const* d_in, const int* in_sizes, int n_in,
                              void* d_out, int out_size) {
    const float* x         = (const float*)d_in[0];
    const float* w0        = (const float*)d_in[1];
    const float* b0        = (const float*)d_in[2];
    const float* w1        = (const float*)d_in[3];
    const float* b1        = (const float*)d_in[4];
    const int*   edge_src0 = (const int*)d_in[5];
    const int*   edge_dst0 = (const int*)d_in[6];
    const int*   edge_src1 = (const int*)d_in[7];
    const int*   edge_dst1 = (const int*)d_in[8];
    const int E0 = in_sizes[5];
    const int E1 = in_sizes[7];

    float *agg0, *h1, *agg1;
    int *cnti, *slots0, *slots1;
    cudaGetSymbolAddress((void**)&agg0,   g_agg0);
    cudaGetSymbolAddress((void**)&h1,     g_h1);
    cudaGetSymbolAddress((void**)&agg1,   g_agg1);
    cudaGetSymbolAddress((void**)&cnti,   g_cnti);
    cudaGetSymbolAddress((void**)&slots0, g_slots0);
    cudaGetSymbolAddress((void**)&slots1, g_slots1);
    int* cnti0 = cnti;
    int* cnti1 = cnti + N1C;

    cudaFuncSetAttribute(sage_gemm_kernel<true>,
                         cudaFuncAttributeMaxDynamicSharedMemorySize, SMEM_GEMM);
    cudaFuncSetAttribute(sage_gemm_kernel<false>,
                         cudaFuncAttributeMaxDynamicSharedMemorySize, SMEM_GEMM);

    // build: 1 memset + 2 fills (no hist, no scan)
    cudaMemsetAsync(cnti, 0, (N1C + N2C) * sizeof(int), 0);
    fill_kernel<<<(E0 + 255) / 256, 256>>>(edge_src0, edge_dst0, cnti0, slots0, E0);  // #1
    fill_kernel<<<(E1 + 255) / 256, 256>>>(edge_src1, edge_dst1, cnti1, slots1, E1);  // #2

    // layer 0
    gather_mean_kernel<<<(N1C * 16 + 255) / 256, 256>>>(x, slots0, cnti0,
                                                        agg0, N1C);                    // #3
    sage_gemm_kernel<true><<<N1C / 64, 256, SMEM_GEMM>>>(x, agg0, w0, b0, h1, N1C);    // #4 (profiled)

    // layer 1
    gather_mean_kernel<<<(N2C * 16 + 255) / 256, 256>>>(h1, slots1, cnti1,
                                                        agg1, N2C);                    // #5
    sage_gemm_kernel<false><<<N2C / 64, 256, SMEM_GEMM>>>(h1, agg1, w1, b1,
                                                          (float*)d_out, N2C);         // #6
}

// round 5
// speedup vs baseline: 2.3204x; 1.1108x over previous
#include <cuda_runtime.h>
#include <cstdint>

#define N0 900000
#define N1C 43008
#define N2C 2048
#define D 64
#define TWO_D 128
#define CAP 96
#define WSTRIDE 132
#define INSTRIDE 132

// ---------------- device-global scratch ------------------------------------
__device__ float g_agg0[N1C * D];
__device__ float g_h1[N1C * D];
__device__ float g_agg1[N2C * D];
__device__ int   g_cnti[N1C + N2C];
__device__ int   g_slots0[N1C * CAP];
__device__ int   g_slots1[N2C * CAP];

// ---------------- build: one fused atomic pass ------------------------------
__global__ void fill2_kernel(const int* __restrict__ es0, const int* __restrict__ ed0,
                             int* __restrict__ c0, int* __restrict__ sl0,
                             const int* __restrict__ es1, const int* __restrict__ ed1,
                             int* __restrict__ c1, int* __restrict__ sl1,
                             int E0, int E1) {
    int e = blockIdx.x * blockDim.x + threadIdx.x;
    if (e < E0) {
        int d = ed0[e];
        int p = atomicAdd(&c0[d], 1);
        if (p < CAP) sl0[d * CAP + p] = es0[e];
    } else if (e < E0 + E1) {
        int e1 = e - E0;
        int d = ed1[e1];
        int p = atomicAdd(&c1[d], 1);
        if (p < CAP) sl1[d * CAP + p] = es1[e1];
    }
}

// ---------------- gather + mean (register accumulation) ---------------------
__global__ void gather_mean_kernel(const float* __restrict__ src_feat,
                                   const int* __restrict__ slots,
                                   const int* __restrict__ cnti,
                                   float* __restrict__ agg, int n) {
    int t = blockIdx.x * blockDim.x + threadIdx.x;
    int g = t >> 4;
    if (g >= n) return;
    int l = t & 15;
    int deg = cnti[g];
    int m = min(deg, CAP);
    const int* sl = slots + (size_t)g * CAP;
    const float4* base = reinterpret_cast<const float4*>(src_feat);
    float4 acc = make_float4(0.f, 0.f, 0.f, 0.f);
    int e = 0;
    for (; e + 8 <= m; e += 8) {
        int4 ia = *reinterpret_cast<const int4*>(sl + e);
        int4 ib = *reinterpret_cast<const int4*>(sl + e + 4);
        float4 v0 = base[(size_t)ia.x * 16 + l];
        float4 v1 = base[(size_t)ia.y * 16 + l];
        float4 v2 = base[(size_t)ia.z * 16 + l];
        float4 v3 = base[(size_t)ia.w * 16 + l];
        float4 v4 = base[(size_t)ib.x * 16 + l];
        float4 v5 = base[(size_t)ib.y * 16 + l];
        float4 v6 = base[(size_t)ib.z * 16 + l];
        float4 v7 = base[(size_t)ib.w * 16 + l];
        acc.x += ((v0.x + v1.x) + (v2.x + v3.x)) + ((v4.x + v5.x) + (v6.x + v7.x));
        acc.y += ((v0.y + v1.y) + (v2.y + v3.y)) + ((v4.y + v5.y) + (v6.y + v7.y));
        acc.z += ((v0.z + v1.z) + (v2.z + v3.z)) + ((v4.z + v5.z) + (v6.z + v7.z));
        acc.w += ((v0.w + v1.w) + (v2.w + v3.w)) + ((v4.w + v5.w) + (v6.w + v7.w));
    }
    for (; e < m; e++) {
        float4 v = base[(size_t)sl[e] * 16 + l];
        acc.x += v.x; acc.y += v.y; acc.z += v.z; acc.w += v.w;
    }
    float scl = 1.0f / fmaxf((float)deg, 1.0f);
    acc.x *= scl; acc.y *= scl; acc.z *= scl; acc.w *= scl;
    reinterpret_cast<float4*>(agg)[(size_t)g * 16 + l] = acc;
}

// ---------------- tf32 mma.sync concat-GEMM ---------------------------------
__device__ __forceinline__ uint32_t f2tf32(float f) {
    uint32_t u;
    asm("cvt.rna.tf32.f32 %0, %1;" : "=r"(u) : "f"(f));
    return u;
}

__device__ __forceinline__ void mma_tf32(float* c, uint32_t a0, uint32_t a1,
                                         uint32_t a2, uint32_t a3,
                                         uint32_t b0, uint32_t b1) {
    asm volatile("mma.sync.aligned.m16n8k8.row.col.f32.tf32.tf32.f32 "
                 "{%0,%1,%2,%3}, {%4,%5,%6,%7}, {%8,%9}, {%0,%1,%2,%3};"
                 : "+f"(c[0]), "+f"(c[1]), "+f"(c[2]), "+f"(c[3])
                 : "r"(a0), "r"(a1), "r"(a2), "r"(a3), "r"(b0), "r"(b1));
}

// 128 rows/CTA, 256 threads (8 warps x 16 rows). C = [self|agg] @ W + b.
template <bool RELU>
__global__ void __launch_bounds__(256)
sage_gemm_tf32(const float* __restrict__ self_feat,
               const float* __restrict__ agg,
               const float* __restrict__ w,   // [2D][D] row-major
               const float* __restrict__ b,   // [D]
               float* __restrict__ out, int n) {
    extern __shared__ uint32_t smu[];
    uint32_t* wsh  = smu;                  // W^T tf32: [64][WSTRIDE]
    uint32_t* insh = smu + D * WSTRIDE;    // A tf32:   [128][INSTRIDE]

    const int tid  = threadIdx.x;
    const int wid  = tid >> 5;
    const int lane = tid & 31;
    const int gid  = lane >> 2;   // 0..7
    const int qid  = lane & 3;    // 0..3
    const int row0 = blockIdx.x * 128;

    // stage W^T (wsh[n][k] = w[k][n]) with tf32 rounding
    for (int i = tid; i < TWO_D * 16; i += 256) {   // 2048 float4
        int k = i >> 4;
        int l = i & 15;           // n-col group
        float4 v = reinterpret_cast<const float4*>(w)[i];
        wsh[(l * 4 + 0) * WSTRIDE + k] = f2tf32(v.x);
        wsh[(l * 4 + 1) * WSTRIDE + k] = f2tf32(v.y);
        wsh[(l * 4 + 2) * WSTRIDE + k] = f2tf32(v.z);
        wsh[(l * 4 + 3) * WSTRIDE + k] = f2tf32(v.w);
    }

    // stage A = [self | agg] rows, tf32
    const float4* sbase = reinterpret_cast<const float4*>(self_feat);
    const float4* abase = reinterpret_cast<const float4*>(agg);
    for (int i = tid; i < 128 * 16; i += 256) {
        int r = i >> 4;
        int l = i & 15;
        size_t gi = (size_t)(row0 + r) * 16 + l;
        float4 s = sbase[gi];
        float4 a = abase[gi];
        uint32_t* dst = insh + r * INSTRIDE + l * 4;
        dst[0] = f2tf32(s.x); dst[1] = f2tf32(s.y);
        dst[2] = f2tf32(s.z); dst[3] = f2tf32(s.w);
        uint32_t* dst2 = dst + D;
        dst2[0] = f2tf32(a.x); dst2[1] = f2tf32(a.y);
        dst2[2] = f2tf32(a.z); dst2[3] = f2tf32(a.w);
    }
    __syncthreads();

    // fragment bases (conflict-free: bank = (4*row + k) mod 32)
    const uint32_t* a_base = insh + (wid * 16 + gid) * INSTRIDE + qid;
    const uint32_t* b_base = wsh + gid * WSTRIDE + qid;

    float c[8][4] = {};
    #pragma unroll
    for (int k0 = 0; k0 < TWO_D; k0 += 8) {
        uint32_t a0 = a_base[k0];
        uint32_t a1 = a_base[8 * INSTRIDE + k0];
        uint32_t a2 = a_base[k0 + 4];
        uint32_t a3 = a_base[8 * INSTRIDE + k0 + 4];
        #pragma unroll
        for (int nt = 0; nt < 8; nt++) {
            uint32_t b0 = b_base[nt * 8 * WSTRIDE + k0];
            uint32_t b1 = b_base[nt * 8 * WSTRIDE + k0 + 4];
            mma_tf32(c[nt], a0, a1, a2, a3, b0, b1);
        }
    }

    // epilogue: bias + relu + store
    int row = row0 + wid * 16 + gid;
    #pragma unroll
    for (int nt = 0; nt < 8; nt++) {
        int col = nt * 8 + qid * 2;
        float2 bv = *reinterpret_cast<const float2*>(b + col);
        float2 r01 = make_float2(c[nt][0] + bv.x, c[nt][1] + bv.y);
        float2 r23 = make_float2(c[nt][2] + bv.x, c[nt][3] + bv.y);
        if (RELU) {
            r01.x = fmaxf(r01.x, 0.f); r01.y = fmaxf(r01.y, 0.f);
            r23.x = fmaxf(r23.x, 0.f); r23.y = fmaxf(r23.y, 0.f);
        }
        *reinterpret_cast<float2*>(out + (size_t)row * D + col) = r01;
        *reinterpret_cast<float2*>(out + (size_t)(row + 8) * D + col) = r23;
    }
}

static const int SMEM_MMA = (D * WSTRIDE + 128 * INSTRIDE) * (int)sizeof(uint32_t);

// ---------------- launch ---------------------------------------------------
extern "C" void kernel_launch(void* const* d_in, const int* in_sizes, int n_in,
                              void* d_out, int out_size) {
    const float* x         = (const float*)d_in[0];
    const float* w0        = (const float*)d_in[1];
    const float* b0        = (const float*)d_in[2];
    const float* w1        = (const float*)d_in[3];
    const float* b1        = (const float*)d_in[4];
    const int*   edge_src0 = (const int*)d_in[5];
    const int*   edge_dst0 = (const int*)d_in[6];
    const int*   edge_src1 = (const int*)d_in[7];
    const int*   edge_dst1 = (const int*)d_in[8];
    const int E0 = in_sizes[5];
    const int E1 = in_sizes[7];

    float *agg0, *h1, *agg1;
    int *cnti, *slots0, *slots1;
    cudaGetSymbolAddress((void**)&agg0,   g_agg0);
    cudaGetSymbolAddress((void**)&h1,     g_h1);
    cudaGetSymbolAddress((void**)&agg1,   g_agg1);
    cudaGetSymbolAddress((void**)&cnti,   g_cnti);
    cudaGetSymbolAddress((void**)&slots0, g_slots0);
    cudaGetSymbolAddress((void**)&slots1, g_slots1);
    int* cnti0 = cnti;
    int* cnti1 = cnti + N1C;

    cudaFuncSetAttribute(sage_gemm_tf32<true>,
                         cudaFuncAttributeMaxDynamicSharedMemorySize, SMEM_MMA);
    cudaFuncSetAttribute(sage_gemm_tf32<false>,
                         cudaFuncAttributeMaxDynamicSharedMemorySize, SMEM_MMA);

    // #0 memset + #1 fused fill
    cudaMemsetAsync(cnti, 0, (N1C + N2C) * sizeof(int), 0);
    int EB = E0 + E1;
    fill2_kernel<<<(EB + 255) / 256, 256>>>(edge_src0, edge_dst0, cnti0, slots0,
                                            edge_src1, edge_dst1, cnti1, slots1,
                                            E0, E1);

    // layer 0
    gather_mean_kernel<<<(N1C * 16 + 255) / 256, 256>>>(x, slots0, cnti0,
                                                        agg0, N1C);           // #2
    sage_gemm_tf32<true><<<N1C / 128, 256, SMEM_MMA>>>(x, agg0, w0, b0,
                                                       h1, N1C);              // #3 (profiled)

    // layer 1
    gather_mean_kernel<<<(N2C * 16 + 255) / 256, 256>>>(h1, slots1, cnti1,
                                                        agg1, N2C);           // #4
    sage_gemm_tf32<false><<<N2C / 128, 256, SMEM_MMA>>>(h1, agg1, w1, b1,
                                                        (float*)d_out, N2C);  // #5
}